// round 1
// baseline (speedup 1.0000x reference)
#include <cuda_runtime.h>
#include <math.h>

#define HDIM  1024
#define IDIM  2816
#define TWOI  5632
#define NEXP  8
#define NTOK  2048
#define NGRP  9   // 8 experts + base (group 8)

// ---------------- scratch (device globals; no allocation) ----------------
__device__ int   g_cnt[NGRP];
__device__ int   g_tok[NGRP * NTOK];          // token index per (group,row)
__device__ int   g_te[NTOK * 2];              // per-token chosen experts
__device__ int   g_tp[NTOK * 2];              // per-token slot within expert group
__device__ float g_tw[NTOK * 2];              // per-token renormalized weights
__device__ float g_act[(size_t)NGRP * NTOK * IDIM];   // SwiGLU activations
__device__ float g_y  [(size_t)NGRP * NTOK * HDIM];   // per-group MLP outputs

// ---------------- init: reset counters ----------------
__global__ void k_init() {
    if (threadIdx.x < NGRP)
        g_cnt[threadIdx.x] = (threadIdx.x == NEXP) ? NTOK : 0;  // base group always full
}

// ---------------- router: warp per token ----------------
__global__ void k_router(const float* __restrict__ x, const float* __restrict__ gw) {
    int gtid = blockIdx.x * blockDim.x + threadIdx.x;
    int t    = gtid >> 5;
    int lane = gtid & 31;
    if (t >= NTOK) return;

    const float* xr = x + (size_t)t * HDIM;
    float acc[NEXP];
#pragma unroll
    for (int e = 0; e < NEXP; e++) acc[e] = 0.f;

    for (int k = lane; k < HDIM; k += 32) {
        float xv = xr[k];
        const float4* gr = (const float4*)(gw + (size_t)k * NEXP);
        float4 g0 = gr[0], g1 = gr[1];
        acc[0] += xv * g0.x; acc[1] += xv * g0.y;
        acc[2] += xv * g0.z; acc[3] += xv * g0.w;
        acc[4] += xv * g1.x; acc[5] += xv * g1.y;
        acc[6] += xv * g1.z; acc[7] += xv * g1.w;
    }
#pragma unroll
    for (int e = 0; e < NEXP; e++) {
#pragma unroll
        for (int off = 16; off; off >>= 1)
            acc[e] += __shfl_xor_sync(0xffffffffu, acc[e], off);
    }

    if (lane == 0) {
        float m = acc[0];
#pragma unroll
        for (int e = 1; e < NEXP; e++) m = fmaxf(m, acc[e]);
        float p[NEXP];
#pragma unroll
        for (int e = 0; e < NEXP; e++) p[e] = expf(acc[e] - m);

        // top-1 (first index wins ties — matches jax top_k)
        int i0 = 0; float b0 = p[0];
#pragma unroll
        for (int e = 1; e < NEXP; e++) if (p[e] > b0) { b0 = p[e]; i0 = e; }
        // top-2
        int i1 = (i0 == 0) ? 1 : 0; float b1 = p[i1];
#pragma unroll
        for (int e = 0; e < NEXP; e++)
            if (e != i0 && p[e] > b1) { b1 = p[e]; i1 = e; }

        float s = b0 + b1;
        int p0 = atomicAdd(&g_cnt[i0], 1);
        int p1 = atomicAdd(&g_cnt[i1], 1);
        g_tok[i0 * NTOK + p0] = t;
        g_tok[i1 * NTOK + p1] = t;
        g_te[2 * t + 0] = i0; g_tp[2 * t + 0] = p0; g_tw[2 * t + 0] = b0 / s;
        g_te[2 * t + 1] = i1; g_tp[2 * t + 1] = p1; g_tw[2 * t + 1] = b1 / s;
        g_tok[NEXP * NTOK + t] = t;   // base group: identity mapping
    }
}

// ---------------- GEMM1: act = silu(x@Wg) * (x@Wu), grouped + gathered ----------------
// Block tile: 64 rows x 64 cols (of I), computing BOTH gate and up columns.
__global__ __launch_bounds__(256) void k_gemm1(const float* __restrict__ x,
                                               const float* __restrict__ base_wgu,
                                               const float* __restrict__ exp_wgu) {
    int g   = blockIdx.z;
    int cnt = g_cnt[g];
    int m0  = blockIdx.y * 64;
    if (m0 >= cnt) return;
    int n0  = blockIdx.x * 64;

    const float* W = (g == NEXP) ? base_wgu : (exp_wgu + (size_t)g * HDIM * TWOI);

    __shared__ int   stok[64];
    __shared__ float As[16][68];
    __shared__ float Bg[16][64];
    __shared__ float Bu[16][64];

    int tid = threadIdx.x;
    if (tid < 64) {
        int r = m0 + tid;
        stok[tid] = g_tok[g * NTOK + ((r < cnt) ? r : (cnt - 1))];
    }
    __syncthreads();

    int ar = tid >> 2, ak = (tid & 3) << 2;   // A loader: row 0..63, k offset 0/4/8/12
    int bk = tid >> 4, bn = (tid & 15) << 2;  // B loader: k 0..15, n offset
    int ty = tid >> 4, tx = tid & 15;         // compute mapping

    const float* arow = x + (size_t)stok[ar] * HDIM;

    float accg[4][4] = {}, accu[4][4] = {};

    for (int kk = 0; kk < HDIM; kk += 16) {
        float4 av = *(const float4*)(arow + kk + ak);
        As[ak + 0][ar] = av.x; As[ak + 1][ar] = av.y;
        As[ak + 2][ar] = av.z; As[ak + 3][ar] = av.w;
        const float* wrow = W + (size_t)(kk + bk) * TWOI + n0 + bn;
        *(float4*)&Bg[bk][bn] = *(const float4*)(wrow);
        *(float4*)&Bu[bk][bn] = *(const float4*)(wrow + IDIM);
        __syncthreads();

#pragma unroll
        for (int k = 0; k < 16; k++) {
            float4 a4  = *(const float4*)&As[k][ty * 4];
            float4 bg4 = *(const float4*)&Bg[k][tx * 4];
            float4 bu4 = *(const float4*)&Bu[k][tx * 4];
            float a[4]  = {a4.x, a4.y, a4.z, a4.w};
            float bg[4] = {bg4.x, bg4.y, bg4.z, bg4.w};
            float bu[4] = {bu4.x, bu4.y, bu4.z, bu4.w};
#pragma unroll
            for (int i = 0; i < 4; i++) {
#pragma unroll
                for (int j = 0; j < 4; j++) {
                    accg[i][j] += a[i] * bg[j];
                    accu[i][j] += a[i] * bu[j];
                }
            }
        }
        __syncthreads();
    }

#pragma unroll
    for (int i = 0; i < 4; i++) {
        int row = m0 + ty * 4 + i;
        if (row >= cnt) continue;
        float4 o;
        float gv;
        gv = accg[i][0]; o.x = accu[i][0] * (gv / (1.f + expf(-gv)));
        gv = accg[i][1]; o.y = accu[i][1] * (gv / (1.f + expf(-gv)));
        gv = accg[i][2]; o.z = accu[i][2] * (gv / (1.f + expf(-gv)));
        gv = accg[i][3]; o.w = accu[i][3] * (gv / (1.f + expf(-gv)));
        *(float4*)&g_act[((size_t)g * NTOK + row) * IDIM + n0 + tx * 4] = o;
    }
}

// ---------------- GEMM2: y = act @ Wd, grouped ----------------
__global__ __launch_bounds__(256) void k_gemm2(const float* __restrict__ base_wd,
                                               const float* __restrict__ exp_wd) {
    int g   = blockIdx.z;
    int cnt = g_cnt[g];
    int m0  = blockIdx.y * 64;
    if (m0 >= cnt) return;
    int n0  = blockIdx.x * 64;

    const float* W = (g == NEXP) ? base_wd : (exp_wd + (size_t)g * IDIM * HDIM);

    __shared__ float As[16][68];
    __shared__ float Bs[16][64];

    int tid = threadIdx.x;
    int ar = tid >> 2, ak = (tid & 3) << 2;
    int bk = tid >> 4, bn = (tid & 15) << 2;
    int ty = tid >> 4, tx = tid & 15;

    const float* arow = g_act + ((size_t)g * NTOK + m0 + ar) * IDIM;

    float acc[4][4] = {};

    for (int kk = 0; kk < IDIM; kk += 16) {
        float4 av = *(const float4*)(arow + kk + ak);
        As[ak + 0][ar] = av.x; As[ak + 1][ar] = av.y;
        As[ak + 2][ar] = av.z; As[ak + 3][ar] = av.w;
        *(float4*)&Bs[bk][bn] = *(const float4*)(W + (size_t)(kk + bk) * HDIM + n0 + bn);
        __syncthreads();

#pragma unroll
        for (int k = 0; k < 16; k++) {
            float4 a4 = *(const float4*)&As[k][ty * 4];
            float4 b4 = *(const float4*)&Bs[k][tx * 4];
            float a[4] = {a4.x, a4.y, a4.z, a4.w};
            float b[4] = {b4.x, b4.y, b4.z, b4.w};
#pragma unroll
            for (int i = 0; i < 4; i++) {
#pragma unroll
                for (int j = 0; j < 4; j++)
                    acc[i][j] += a[i] * b[j];
            }
        }
        __syncthreads();
    }

#pragma unroll
    for (int i = 0; i < 4; i++) {
        int row = m0 + ty * 4 + i;
        if (row >= cnt) continue;
        float4 o = make_float4(acc[i][0], acc[i][1], acc[i][2], acc[i][3]);
        *(float4*)&g_y[((size_t)g * NTOK + row) * HDIM + n0 + tx * 4] = o;
    }
}

// ---------------- combine: out = y_base + w0*y_e0 + w1*y_e1 (deterministic) ----------------
__global__ void k_combine(float* __restrict__ out) {
    int idx = blockIdx.x * blockDim.x + threadIdx.x;  // over NTOK * (HDIM/4)
    int t  = idx >> 8;              // HDIM/4 == 256
    int h4 = (idx & 255) << 2;
    if (t >= NTOK) return;

    int   e0 = g_te[2 * t + 0], p0 = g_tp[2 * t + 0];
    int   e1 = g_te[2 * t + 1], p1 = g_tp[2 * t + 1];
    float w0 = g_tw[2 * t + 0], w1 = g_tw[2 * t + 1];

    float4 yb = *(const float4*)&g_y[((size_t)NEXP * NTOK + t ) * HDIM + h4];
    float4 y0 = *(const float4*)&g_y[((size_t)e0   * NTOK + p0) * HDIM + h4];
    float4 y1 = *(const float4*)&g_y[((size_t)e1   * NTOK + p1) * HDIM + h4];

    float4 o;
    o.x = yb.x + w0 * y0.x + w1 * y1.x;
    o.y = yb.y + w0 * y0.y + w1 * y1.y;
    o.z = yb.z + w0 * y0.z + w1 * y1.z;
    o.w = yb.w + w0 * y0.w + w1 * y1.w;
    *(float4*)&out[(size_t)t * HDIM + h4] = o;
}

// ---------------- launch ----------------
extern "C" void kernel_launch(void* const* d_in, const int* in_sizes, int n_in,
                              void* d_out, int out_size) {
    const float* x        = (const float*)d_in[0];
    const float* gate_w   = (const float*)d_in[1];
    const float* base_wgu = (const float*)d_in[2];
    const float* base_wd  = (const float*)d_in[3];
    const float* exp_wgu  = (const float*)d_in[4];
    const float* exp_wd   = (const float*)d_in[5];
    float* out = (float*)d_out;

    k_init<<<1, 32>>>();
    k_router<<<(NTOK * 32) / 256, 256>>>(x, gate_w);
    k_gemm1<<<dim3(IDIM / 64, NTOK / 64, NGRP), 256>>>(x, base_wgu, exp_wgu);
    k_gemm2<<<dim3(HDIM / 64, NTOK / 64, NGRP), 256>>>(base_wd, exp_wd);
    k_combine<<<(NTOK * (HDIM / 4)) / 256, 256>>>(out);
}

// round 2
// speedup vs baseline: 2.6641x; 2.6641x over previous
#include <cuda_runtime.h>
#include <math.h>
#include <stdint.h>

#define HDIM  1024
#define IDIM  2816
#define TWOI  5632
#define NEXP  8
#define NTOK  2048
#define NGRP  9   // 8 experts + base (group 8)

// ---------------- scratch (device globals; no allocation) ----------------
__device__ int   g_cnt[NGRP];
__device__ int   g_tok[NGRP * NTOK];
__device__ int   g_te[NTOK * 2];
__device__ int   g_tp[NTOK * 2];
__device__ float g_tw[NTOK * 2];
__device__ float g_act[(size_t)NGRP * NTOK * IDIM];
__device__ float g_y  [(size_t)NGRP * NTOK * HDIM];

__device__ __forceinline__ float to_tf32(float x) {
    float r;
    asm("cvt.rna.tf32.f32 %0, %1;" : "=f"(r) : "f"(x));
    return r;
}

#define MMA_TF32(C, A, B)                                                     \
    asm volatile(                                                             \
        "mma.sync.aligned.m16n8k8.row.col.f32.tf32.tf32.f32 "                 \
        "{%0,%1,%2,%3}, {%4,%5,%6,%7}, {%8,%9}, {%0,%1,%2,%3};"               \
        : "+f"((C)[0]), "+f"((C)[1]), "+f"((C)[2]), "+f"((C)[3])              \
        : "r"((A)[0]), "r"((A)[1]), "r"((A)[2]), "r"((A)[3]),                 \
          "r"((B)[0]), "r"((B)[1]))

// ---------------- init ----------------
__global__ void k_init() {
    if (threadIdx.x < NGRP)
        g_cnt[threadIdx.x] = (threadIdx.x == NEXP) ? NTOK : 0;
}

// ---------------- router: warp per token ----------------
__global__ void k_router(const float* __restrict__ x, const float* __restrict__ gw) {
    int gtid = blockIdx.x * blockDim.x + threadIdx.x;
    int t    = gtid >> 5;
    int lane = gtid & 31;
    if (t >= NTOK) return;

    const float* xr = x + (size_t)t * HDIM;
    float acc[NEXP];
#pragma unroll
    for (int e = 0; e < NEXP; e++) acc[e] = 0.f;

    for (int k = lane; k < HDIM; k += 32) {
        float xv = xr[k];
        const float4* gr = (const float4*)(gw + (size_t)k * NEXP);
        float4 g0 = gr[0], g1 = gr[1];
        acc[0] += xv * g0.x; acc[1] += xv * g0.y;
        acc[2] += xv * g0.z; acc[3] += xv * g0.w;
        acc[4] += xv * g1.x; acc[5] += xv * g1.y;
        acc[6] += xv * g1.z; acc[7] += xv * g1.w;
    }
#pragma unroll
    for (int e = 0; e < NEXP; e++) {
#pragma unroll
        for (int off = 16; off; off >>= 1)
            acc[e] += __shfl_xor_sync(0xffffffffu, acc[e], off);
    }

    if (lane == 0) {
        float m = acc[0];
#pragma unroll
        for (int e = 1; e < NEXP; e++) m = fmaxf(m, acc[e]);
        float p[NEXP];
#pragma unroll
        for (int e = 0; e < NEXP; e++) p[e] = expf(acc[e] - m);

        int i0 = 0; float b0 = p[0];
#pragma unroll
        for (int e = 1; e < NEXP; e++) if (p[e] > b0) { b0 = p[e]; i0 = e; }
        int i1 = (i0 == 0) ? 1 : 0; float b1 = p[i1];
#pragma unroll
        for (int e = 0; e < NEXP; e++)
            if (e != i0 && p[e] > b1) { b1 = p[e]; i1 = e; }

        float s = b0 + b1;
        int p0 = atomicAdd(&g_cnt[i0], 1);
        int p1 = atomicAdd(&g_cnt[i1], 1);
        g_tok[i0 * NTOK + p0] = t;
        g_tok[i1 * NTOK + p1] = t;
        g_te[2 * t + 0] = i0; g_tp[2 * t + 0] = p0; g_tw[2 * t + 0] = b0 / s;
        g_te[2 * t + 1] = i1; g_tp[2 * t + 1] = p1; g_tw[2 * t + 1] = b1 / s;
        g_tok[NEXP * NTOK + t] = t;
    }
}

// ============================================================================
// GEMM1 (TF32 tensor cores): act = silu(x@Wg) * (x@Wu)
// Block: 128 rows x 64 cols (both gate & up). 8 warps (4m x 2n), warp = 32x32.
// ============================================================================
#define AS_STRIDE 20   // 16 + 4 pad: conflict-free for A-fragment lds
#define BS_STRIDE 72   // 64 + 8 pad: conflict-free for B-fragment lds

__global__ __launch_bounds__(256) void k_gemm1(const float* __restrict__ x,
                                               const float* __restrict__ base_wgu,
                                               const float* __restrict__ exp_wgu) {
    int g   = blockIdx.z;
    int cnt = g_cnt[g];
    int m0  = blockIdx.y * 128;
    if (m0 >= cnt) return;
    int n0  = blockIdx.x * 64;

    const float* W = (g == NEXP) ? base_wgu : (exp_wgu + (size_t)g * HDIM * TWOI);

    __shared__ int   stok[128];
    __shared__ float As[128 * AS_STRIDE];
    __shared__ float Bg[16 * BS_STRIDE];
    __shared__ float Bu[16 * BS_STRIDE];

    int tid  = threadIdx.x;
    int wid  = tid >> 5, lane = tid & 31;
    int wm   = wid & 3, wn = wid >> 2;       // 4 x 2 warp grid
    int qg   = lane >> 2, qq = lane & 3;     // fragment coords

    if (tid < 128) {
        int r = m0 + tid;
        stok[tid] = g_tok[g * NTOK + ((r < cnt) ? r : (cnt - 1))];
    }
    __syncthreads();

    // loader mapping
    int rowA = tid >> 2;               // 0..63
    int k4   = (tid & 3) << 2;         // 0,4,8,12
    int bkr  = tid >> 4;               // 0..15
    int c4   = (tid & 15) << 2;        // 0..60

    const float* pA0 = x + (size_t)stok[rowA]      * HDIM + k4;
    const float* pA1 = x + (size_t)stok[rowA + 64] * HDIM + k4;
    const float* pBg = W + (size_t)bkr * TWOI + n0 + c4;
    const float* pBu = pBg + IDIM;

    float accg[2][4][4] = {}, accu[2][4][4] = {};

    float4 rA0 = *(const float4*)(pA0);
    float4 rA1 = *(const float4*)(pA1);
    float4 rBg = *(const float4*)(pBg);
    float4 rBu = *(const float4*)(pBu);

    for (int kk = 0; kk < HDIM; kk += 16) {
        // stage regs -> smem (tf32-rounded)
        float* a0 = &As[rowA * AS_STRIDE + k4];
        a0[0] = to_tf32(rA0.x); a0[1] = to_tf32(rA0.y);
        a0[2] = to_tf32(rA0.z); a0[3] = to_tf32(rA0.w);
        float* a1 = &As[(rowA + 64) * AS_STRIDE + k4];
        a1[0] = to_tf32(rA1.x); a1[1] = to_tf32(rA1.y);
        a1[2] = to_tf32(rA1.z); a1[3] = to_tf32(rA1.w);
        float* bg = &Bg[bkr * BS_STRIDE + c4];
        bg[0] = to_tf32(rBg.x); bg[1] = to_tf32(rBg.y);
        bg[2] = to_tf32(rBg.z); bg[3] = to_tf32(rBg.w);
        float* bu = &Bu[bkr * BS_STRIDE + c4];
        bu[0] = to_tf32(rBu.x); bu[1] = to_tf32(rBu.y);
        bu[2] = to_tf32(rBu.z); bu[3] = to_tf32(rBu.w);
        __syncthreads();

        if (kk + 16 < HDIM) {  // prefetch next tile
            rA0 = *(const float4*)(pA0 + kk + 16);
            rA1 = *(const float4*)(pA1 + kk + 16);
            rBg = *(const float4*)(pBg + (size_t)16 * TWOI + (size_t)kk * TWOI);
            rBu = *(const float4*)(pBu + (size_t)16 * TWOI + (size_t)kk * TWOI);
        }

#pragma unroll
        for (int ks = 0; ks < 2; ks++) {
            int k0 = ks * 8;
            uint32_t af[2][4];
#pragma unroll
            for (int mt = 0; mt < 2; mt++) {
                int r = wm * 32 + mt * 16 + qg;
                af[mt][0] = __float_as_uint(As[r * AS_STRIDE + k0 + qq]);
                af[mt][1] = __float_as_uint(As[(r + 8) * AS_STRIDE + k0 + qq]);
                af[mt][2] = __float_as_uint(As[r * AS_STRIDE + k0 + qq + 4]);
                af[mt][3] = __float_as_uint(As[(r + 8) * AS_STRIDE + k0 + qq + 4]);
            }
            uint32_t bfg[4][2], bfu[4][2];
#pragma unroll
            for (int nt = 0; nt < 4; nt++) {
                int c = wn * 32 + nt * 8 + qg;
                bfg[nt][0] = __float_as_uint(Bg[(k0 + qq) * BS_STRIDE + c]);
                bfg[nt][1] = __float_as_uint(Bg[(k0 + qq + 4) * BS_STRIDE + c]);
                bfu[nt][0] = __float_as_uint(Bu[(k0 + qq) * BS_STRIDE + c]);
                bfu[nt][1] = __float_as_uint(Bu[(k0 + qq + 4) * BS_STRIDE + c]);
            }
#pragma unroll
            for (int mt = 0; mt < 2; mt++)
#pragma unroll
                for (int nt = 0; nt < 4; nt++) {
                    MMA_TF32(accg[mt][nt], af[mt], bfg[nt]);
                    MMA_TF32(accu[mt][nt], af[mt], bfu[nt]);
                }
        }
        __syncthreads();
    }

    // epilogue: SwiGLU, store float2 pairs
#pragma unroll
    for (int mt = 0; mt < 2; mt++) {
#pragma unroll
        for (int nt = 0; nt < 4; nt++) {
            int c = n0 + wn * 32 + nt * 8 + 2 * qq;
#pragma unroll
            for (int h = 0; h < 2; h++) {   // h=0 -> rows +qg, h=1 -> +qg+8
                int row = m0 + wm * 32 + mt * 16 + qg + h * 8;
                if (row >= cnt) continue;
                float gv0 = accg[mt][nt][2 * h + 0], uv0 = accu[mt][nt][2 * h + 0];
                float gv1 = accg[mt][nt][2 * h + 1], uv1 = accu[mt][nt][2 * h + 1];
                float2 o;
                o.x = uv0 * (gv0 / (1.f + expf(-gv0)));
                o.y = uv1 * (gv1 / (1.f + expf(-gv1)));
                *(float2*)&g_act[((size_t)g * NTOK + row) * IDIM + c] = o;
            }
        }
    }
}

// ============================================================================
// GEMM2 (TF32 tensor cores): y = act @ Wd.  Block 128x64, same warp layout.
// ============================================================================
__global__ __launch_bounds__(256) void k_gemm2(const float* __restrict__ base_wd,
                                               const float* __restrict__ exp_wd) {
    int g   = blockIdx.z;
    int cnt = g_cnt[g];
    int m0  = blockIdx.y * 128;
    if (m0 >= cnt) return;
    int n0  = blockIdx.x * 64;

    const float* W = (g == NEXP) ? base_wd : (exp_wd + (size_t)g * IDIM * HDIM);

    __shared__ float As[128 * AS_STRIDE];
    __shared__ float Bs[16 * BS_STRIDE];

    int tid  = threadIdx.x;
    int wid  = tid >> 5, lane = tid & 31;
    int wm   = wid & 3, wn = wid >> 2;
    int qg   = lane >> 2, qq = lane & 3;

    int rowA = tid >> 2;
    int k4   = (tid & 3) << 2;
    int bkr  = tid >> 4;
    int c4   = (tid & 15) << 2;

    const float* pA0 = g_act + ((size_t)g * NTOK + m0 + rowA)      * IDIM + k4;
    const float* pA1 = g_act + ((size_t)g * NTOK + m0 + rowA + 64) * IDIM + k4;
    const float* pB  = W + (size_t)bkr * HDIM + n0 + c4;

    float acc[2][4][4] = {};

    float4 rA0 = *(const float4*)(pA0);
    float4 rA1 = *(const float4*)(pA1);
    float4 rB  = *(const float4*)(pB);

    for (int kk = 0; kk < IDIM; kk += 16) {
        float* a0 = &As[rowA * AS_STRIDE + k4];
        a0[0] = to_tf32(rA0.x); a0[1] = to_tf32(rA0.y);
        a0[2] = to_tf32(rA0.z); a0[3] = to_tf32(rA0.w);
        float* a1 = &As[(rowA + 64) * AS_STRIDE + k4];
        a1[0] = to_tf32(rA1.x); a1[1] = to_tf32(rA1.y);
        a1[2] = to_tf32(rA1.z); a1[3] = to_tf32(rA1.w);
        float* b0 = &Bs[bkr * BS_STRIDE + c4];
        b0[0] = to_tf32(rB.x); b0[1] = to_tf32(rB.y);
        b0[2] = to_tf32(rB.z); b0[3] = to_tf32(rB.w);
        __syncthreads();

        if (kk + 16 < IDIM) {
            rA0 = *(const float4*)(pA0 + kk + 16);
            rA1 = *(const float4*)(pA1 + kk + 16);
            rB  = *(const float4*)(pB + (size_t)(kk + 16) * HDIM);
        }

#pragma unroll
        for (int ks = 0; ks < 2; ks++) {
            int k0 = ks * 8;
            uint32_t af[2][4];
#pragma unroll
            for (int mt = 0; mt < 2; mt++) {
                int r = wm * 32 + mt * 16 + qg;
                af[mt][0] = __float_as_uint(As[r * AS_STRIDE + k0 + qq]);
                af[mt][1] = __float_as_uint(As[(r + 8) * AS_STRIDE + k0 + qq]);
                af[mt][2] = __float_as_uint(As[r * AS_STRIDE + k0 + qq + 4]);
                af[mt][3] = __float_as_uint(As[(r + 8) * AS_STRIDE + k0 + qq + 4]);
            }
            uint32_t bf[4][2];
#pragma unroll
            for (int nt = 0; nt < 4; nt++) {
                int c = wn * 32 + nt * 8 + qg;
                bf[nt][0] = __float_as_uint(Bs[(k0 + qq) * BS_STRIDE + c]);
                bf[nt][1] = __float_as_uint(Bs[(k0 + qq + 4) * BS_STRIDE + c]);
            }
#pragma unroll
            for (int mt = 0; mt < 2; mt++)
#pragma unroll
                for (int nt = 0; nt < 4; nt++)
                    MMA_TF32(acc[mt][nt], af[mt], bf[nt]);
        }
        __syncthreads();
    }

#pragma unroll
    for (int mt = 0; mt < 2; mt++) {
#pragma unroll
        for (int nt = 0; nt < 4; nt++) {
            int c = n0 + wn * 32 + nt * 8 + 2 * qq;
#pragma unroll
            for (int h = 0; h < 2; h++) {
                int row = m0 + wm * 32 + mt * 16 + qg + h * 8;
                if (row >= cnt) continue;
                float2 o = make_float2(acc[mt][nt][2 * h + 0], acc[mt][nt][2 * h + 1]);
                *(float2*)&g_y[((size_t)g * NTOK + row) * HDIM + c] = o;
            }
        }
    }
}

// ---------------- combine ----------------
__global__ void k_combine(float* __restrict__ out) {
    int idx = blockIdx.x * blockDim.x + threadIdx.x;
    int t  = idx >> 8;
    int h4 = (idx & 255) << 2;
    if (t >= NTOK) return;

    int   e0 = g_te[2 * t + 0], p0 = g_tp[2 * t + 0];
    int   e1 = g_te[2 * t + 1], p1 = g_tp[2 * t + 1];
    float w0 = g_tw[2 * t + 0], w1 = g_tw[2 * t + 1];

    float4 yb = *(const float4*)&g_y[((size_t)NEXP * NTOK + t ) * HDIM + h4];
    float4 y0 = *(const float4*)&g_y[((size_t)e0   * NTOK + p0) * HDIM + h4];
    float4 y1 = *(const float4*)&g_y[((size_t)e1   * NTOK + p1) * HDIM + h4];

    float4 o;
    o.x = yb.x + w0 * y0.x + w1 * y1.x;
    o.y = yb.y + w0 * y0.y + w1 * y1.y;
    o.z = yb.z + w0 * y0.z + w1 * y1.z;
    o.w = yb.w + w0 * y0.w + w1 * y1.w;
    *(float4*)&out[(size_t)t * HDIM + h4] = o;
}

// ---------------- launch ----------------
extern "C" void kernel_launch(void* const* d_in, const int* in_sizes, int n_in,
                              void* d_out, int out_size) {
    const float* x        = (const float*)d_in[0];
    const float* gate_w   = (const float*)d_in[1];
    const float* base_wgu = (const float*)d_in[2];
    const float* base_wd  = (const float*)d_in[3];
    const float* exp_wgu  = (const float*)d_in[4];
    const float* exp_wd   = (const float*)d_in[5];
    float* out = (float*)d_out;

    k_init<<<1, 32>>>();
    k_router<<<(NTOK * 32) / 256, 256>>>(x, gate_w);
    k_gemm1<<<dim3(IDIM / 64, NTOK / 128, NGRP), 256>>>(x, base_wgu, exp_wgu);
    k_gemm2<<<dim3(HDIM / 64, NTOK / 128, NGRP), 256>>>(base_wd, exp_wd);
    k_combine<<<(NTOK * (HDIM / 4)) / 256, 256>>>(out);
}